// round 15
// baseline (speedup 1.0000x reference)
#include <cuda_runtime.h>
#include <cuda_bf16.h>
#include <stdint.h>
#include <float.h>

typedef unsigned long long ull;

#define TOKENS 16384
#define DIM    256
#define KW     8192

#define BM     128
#define BN     128
#define SPLIT  16
#define NRANGE (KW / SPLIT)        // 512 codes per split
#define FSPLITS 12                 // splits 0..11 -> FFMA2 (exact)
// splits 12..15 -> bf16 mma (top-2 + margin + rescue)

// ---- FFMA2 path geometry ----
#define BK     32
#define FSTAGES ((NRANGE / BN) * (DIM / BK))   // 4 * 8 = 32
#define SW     128
#define FTILEB (BK * SW * 4)        // 16384
#define FBUFB  (2 * FTILEB)         // 32768 (x + w)
#define FNBUF  3                    // 98304

// ---- bf16 mma path geometry ----
#define BK16   64
#define MSTAGES ((NRANGE / BN) * (DIM / BK16)) // 4 * 4 = 16
#define ROWB   144
#define MTILEB (128 * ROWB)         // 18432
#define MBUFB  (2 * MTILEB)         // 36864
#define MNBUF  3                    // 110592

#define SMEM_BYTES (MNBUF * MBUFB)  // 110592 (max of both paths)

#define MARGIN 0.75f

// ---------------- device scratch ----------------
__device__ float g_wn[KW];
__device__ float g_pval[TOKENS * SPLIT];
__device__ float g_pval2[TOKENS * SPLIT];
__device__ int   g_pidx[TOKENS * SPLIT];
__device__ int   g_flag[TOKENS];
__device__ float g_xT[(size_t)DIM * TOKENS];        // [d][token] fp32
__device__ float g_wT[(size_t)DIM * KW];            // [d][code]  fp32
__device__ __nv_bfloat16 g_xh[(size_t)TOKENS * DIM];  // row-major bf16
__device__ __nv_bfloat16 g_wh[(size_t)KW * DIM];

// ---------------- helpers ----------------
__device__ __forceinline__ uint32_t smem_u32(const void* p) {
    uint32_t a;
    asm("{ .reg .u64 t; cvta.to.shared.u64 t, %1; cvt.u32.u64 %0, t; }" : "=r"(a) : "l"(p));
    return a;
}
#define CP_ASYNC16(dst, src) \
    asm volatile("cp.async.cg.shared.global [%0], [%1], 16;" :: "r"(dst), "l"(src) : "memory")
#define LDSM_X4(r0, r1, r2, r3, addr) \
    asm volatile("ldmatrix.sync.aligned.m8n8.x4.shared.b16 {%0,%1,%2,%3}, [%4];" \
                 : "=r"(r0), "=r"(r1), "=r"(r2), "=r"(r3) : "r"(addr))
#define MMA_BF16(c, a0, a1, a2, a3, b0, b1) \
    asm volatile("mma.sync.aligned.m16n8k16.row.col.f32.bf16.bf16.f32 " \
                 "{%0,%1,%2,%3}, {%4,%5,%6,%7}, {%8,%9}, {%0,%1,%2,%3};" \
                 : "+f"((c)[0]), "+f"((c)[1]), "+f"((c)[2]), "+f"((c)[3]) \
                 : "r"(a0), "r"(a1), "r"(a2), "r"(a3), "r"(b0), "r"(b1))

__device__ __forceinline__ void top2_ins(float s, int n, float& v1, int& i1, float& v2) {
    if (s > v1 || (s == v1 && n < i1)) { v2 = v1; v1 = s; i1 = n; }
    else if (s > v2) v2 = s;
}
__device__ __forceinline__ void top2_mrg(float ov1, int oi1, float ov2,
                                         float& v1, int& i1, float& v2) {
    if (ov1 > v1 || (ov1 == v1 && oi1 < i1)) { v2 = fmaxf(v1, ov2); v1 = ov1; i1 = oi1; }
    else v2 = fmaxf(v2, ov1);
}

// ---------------- prepass ----------------
__global__ void transpose_kernel(const float* __restrict__ src, float* __restrict__ dst,
                                 int rows) {
    __shared__ float t[32][33];
    const int c0 = blockIdx.x * 32;
    const int r0 = blockIdx.y * 32;
#pragma unroll
    for (int i = 0; i < 4; i++)
        t[threadIdx.y + 8 * i][threadIdx.x] =
            src[(size_t)(r0 + threadIdx.y + 8 * i) * DIM + c0 + threadIdx.x];
    __syncthreads();
#pragma unroll
    for (int i = 0; i < 4; i++)
        dst[(size_t)(c0 + threadIdx.y + 8 * i) * rows + r0 + threadIdx.x] =
            t[threadIdx.x][threadIdx.y + 8 * i];
}

// bf16 convert (x & w) + w row norms
__global__ void convert_norm_kernel(const float* __restrict__ x, const float* __restrict__ w) {
    const int b = blockIdx.x;
    if (b < TOKENS * DIM / 4 / 256) {
        const int i = b * 256 + threadIdx.x;
        const float4 v = ((const float4*)x)[i];
        ((__nv_bfloat162*)g_xh)[i * 2]     = __floats2bfloat162_rn(v.x, v.y);
        ((__nv_bfloat162*)g_xh)[i * 2 + 1] = __floats2bfloat162_rn(v.z, v.w);
    } else {
        const int row = (b - TOKENS * DIM / 4 / 256) * 256 + threadIdx.x;
        const float4* src = (const float4*)(w + (size_t)row * DIM);
        __nv_bfloat162* dst = (__nv_bfloat162*)(g_wh + (size_t)row * DIM);
        float s = 0.f;
#pragma unroll
        for (int c = 0; c < DIM / 4; c++) {
            const float4 v = __ldg(src + c);
            s += v.x * v.x + v.y * v.y + v.z * v.z + v.w * v.w;
            dst[c * 2]     = __floats2bfloat162_rn(v.x, v.y);
            dst[c * 2 + 1] = __floats2bfloat162_rn(v.z, v.w);
        }
        g_wn[row] = s;
    }
}

// ---------------- hybrid main kernel ----------------
extern __shared__ char dynsmem[];

// ===== FFMA2 path (R12, exact fp32) =====
__device__ __forceinline__ void ffma_load(uint32_t sbase, int gs, int tid,
                                          int mbase, int nbase0) {
    if (gs < FSTAGES) {
        const int buf = gs % FNBUF;
        const int dt = (gs & 7) * BK;
        const int nb = nbase0 + (gs >> 3) * BN;
        const uint32_t xb = sbase + buf * FBUFB;
        const uint32_t wb = xb + FTILEB;
#pragma unroll
        for (int i = 0; i < 4; i++) {
            const int idx = tid + 256 * i;
            const int row = idx >> 5, col = idx & 31;
            CP_ASYNC16(xb + row * (SW * 4) + col * 16,
                       g_xT + (size_t)(dt + row) * TOKENS + mbase + col * 4);
            CP_ASYNC16(wb + row * (SW * 4) + col * 16,
                       g_wT + (size_t)(dt + row) * KW + nb + col * 4);
        }
    }
    asm volatile("cp.async.commit_group;" ::: "memory");
}

__device__ void ffma_path(char* sm, int tid, int mbase, int sidx) {
    const uint32_t sbase = smem_u32(sm);
    const int tx = tid & 15;
    const int ty = tid >> 4;
    const int nbase0 = sidx * NRANGE;

    ull acc[4][8];
#pragma unroll
    for (int p = 0; p < 4; p++)
#pragma unroll
        for (int j = 0; j < 8; j++) acc[p][j] = 0ull;

    float bv[8];
    int   bi[8];
#pragma unroll
    for (int t = 0; t < 8; t++) { bv[t] = -FLT_MAX; bi[t] = 0x7fffffff; }

    ffma_load(sbase, 0, tid, mbase, nbase0);

    for (int gs = 0; gs < FSTAGES; gs++) {
        ffma_load(sbase, gs + 1, tid, mbase, nbase0);
        asm volatile("cp.async.wait_group 1;" ::: "memory");
        __syncthreads();

        const float* xsp = (const float*)(sm + (gs % FNBUF) * FBUFB);
        const float* wsp = (const float*)(sm + (gs % FNBUF) * FBUFB + FTILEB);

#pragma unroll
        for (int k = 0; k < BK; k++) {
            const ulonglong2* xrow = (const ulonglong2*)(xsp + k * SW + ty * 8);
            ulonglong2 xq0 = xrow[0];
            ulonglong2 xq1 = xrow[1];
            ull w2[8];
#pragma unroll
            for (int j = 0; j < 8; j++) {
                float wv = wsp[k * SW + tx + 16 * j];
                asm("mov.b64 %0, {%1, %1};" : "=l"(w2[j]) : "f"(wv));
            }
#pragma unroll
            for (int j = 0; j < 8; j++) {
                asm("fma.rn.f32x2 %0, %1, %2, %0;" : "+l"(acc[0][j]) : "l"(xq0.x), "l"(w2[j]));
                asm("fma.rn.f32x2 %0, %1, %2, %0;" : "+l"(acc[1][j]) : "l"(xq0.y), "l"(w2[j]));
                asm("fma.rn.f32x2 %0, %1, %2, %0;" : "+l"(acc[2][j]) : "l"(xq1.x), "l"(w2[j]));
                asm("fma.rn.f32x2 %0, %1, %2, %0;" : "+l"(acc[3][j]) : "l"(xq1.y), "l"(w2[j]));
            }
        }

        if ((gs & 7) == 7) {
            const int nb = nbase0 + (gs >> 3) * BN;
#pragma unroll
            for (int j = 0; j < 8; j++) {
                const int n = nb + tx + 16 * j;
                const float wn = __ldg(&g_wn[n]);
#pragma unroll
                for (int p = 0; p < 4; p++) {
                    float lo, hi;
                    asm("mov.b64 {%0, %1}, %2;" : "=f"(lo), "=f"(hi) : "l"(acc[p][j]));
                    const float s0 = wn - 2.f * lo;
                    const float s1 = wn - 2.f * hi;
                    const int t0 = 2 * p, t1 = 2 * p + 1;
                    if (s0 > bv[t0] || (s0 == bv[t0] && n < bi[t0])) { bv[t0] = s0; bi[t0] = n; }
                    if (s1 > bv[t1] || (s1 == bv[t1] && n < bi[t1])) { bv[t1] = s1; bi[t1] = n; }
                    acc[p][j] = 0ull;
                }
            }
        }
    }

#pragma unroll
    for (int off = 8; off >= 1; off >>= 1) {
#pragma unroll
        for (int t = 0; t < 8; t++) {
            float ov = __shfl_xor_sync(0xffffffffu, bv[t], off);
            int   oi = __shfl_xor_sync(0xffffffffu, bi[t], off);
            if (ov > bv[t] || (ov == bv[t] && oi < bi[t])) { bv[t] = ov; bi[t] = oi; }
        }
    }

    if (tx == 0) {
#pragma unroll
        for (int t = 0; t < 8; t++) {
            const int tok = mbase + ty * 8 + t;
            g_pval[tok * SPLIT + sidx]  = bv[t];
            g_pidx[tok * SPLIT + sidx]  = bi[t];
            g_pval2[tok * SPLIT + sidx] = -FLT_MAX;   // exact: never triggers margin
        }
    }
}

// ===== bf16 mma path (R5 structure, top-2) =====
__device__ __forceinline__ void mma_load(uint32_t sbase, int gs, int tid,
                                         int mbase, int nbase0) {
    if (gs < MSTAGES) {
        const int buf = gs % MNBUF;
        const int kb = (gs & 3) * BK16;
        const int nb = nbase0 + (gs >> 2) * BN;
        const uint32_t base = sbase + buf * MBUFB;
        const int col = tid & 7;
        const int r0 = tid >> 3;
#pragma unroll
        for (int i = 0; i < 4; i++) {
            const int r = r0 + 32 * i;
            CP_ASYNC16(base + r * ROWB + col * 16,
                       g_xh + (size_t)(mbase + r) * DIM + kb + col * 8);
            CP_ASYNC16(base + MTILEB + r * ROWB + col * 16,
                       g_wh + (size_t)(nb + r) * DIM + kb + col * 8);
        }
    }
    asm volatile("cp.async.commit_group;" ::: "memory");
}

__device__ void mma_path(char* sm, int tid, int mbase, int sidx) {
    const uint32_t sbase = smem_u32(sm);
    const int lane = tid & 31;
    const int wid = tid >> 5;
    const int warp_m = wid >> 2;
    const int warp_n = wid & 3;
    const int nbase0 = sidx * NRANGE;

    const uint32_t aOff = (uint32_t)(warp_m * 64 + ((lane >> 3) & 1) * 8 + (lane & 7)) * ROWB
                        + ((lane >> 4) & 1) * 16;
    const uint32_t bOff = (uint32_t)(warp_n * 32 + ((lane >> 4) & 1) * 8 + (lane & 7)) * ROWB
                        + ((lane >> 3) & 1) * 16;

    float acc[4][4][4];
#pragma unroll
    for (int f = 0; f < 4; f++)
#pragma unroll
        for (int j = 0; j < 4; j++)
#pragma unroll
            for (int e = 0; e < 4; e++) acc[f][j][e] = 0.f;

    float bv[8], bv2[8];
    int   bi[8];
#pragma unroll
    for (int t = 0; t < 8; t++) { bv[t] = -FLT_MAX; bv2[t] = -FLT_MAX; bi[t] = 0x7fffffff; }

    mma_load(sbase, 0, tid, mbase, nbase0);
    mma_load(sbase, 1, tid, mbase, nbase0);

    for (int gs = 0; gs < MSTAGES; gs++) {
        if (gs + 1 < MSTAGES)
            asm volatile("cp.async.wait_group 1;" ::: "memory");
        else
            asm volatile("cp.async.wait_group 0;" ::: "memory");
        __syncthreads();

        if (gs + 2 < MSTAGES)
            mma_load(sbase, gs + 2, tid, mbase, nbase0);

        const uint32_t abase = sbase + (gs % MNBUF) * MBUFB;
        const uint32_t bbase = abase + MTILEB;

#pragma unroll
        for (int k = 0; k < BK16 / 16; k++) {
            uint32_t a[4][4];
#pragma unroll
            for (int f = 0; f < 4; f++)
                LDSM_X4(a[f][0], a[f][1], a[f][2], a[f][3],
                        abase + aOff + f * 16 * ROWB + k * 32);
            uint32_t b[8];
            LDSM_X4(b[0], b[1], b[2], b[3], bbase + bOff + k * 32);
            LDSM_X4(b[4], b[5], b[6], b[7], bbase + bOff + 16 * ROWB + k * 32);
#pragma unroll
            for (int f = 0; f < 4; f++)
#pragma unroll
                for (int j = 0; j < 4; j++)
                    MMA_BF16(acc[f][j], a[f][0], a[f][1], a[f][2], a[f][3],
                             b[2 * j], b[2 * j + 1]);
        }

        if ((gs & 3) == 3) {
            const int nb = nbase0 + (gs >> 2) * BN;
#pragma unroll
            for (int f = 0; f < 4; f++) {
#pragma unroll
                for (int j = 0; j < 4; j++) {
                    const int n0 = nb + warp_n * 32 + j * 8 + (lane & 3) * 2;
                    const float wn0 = __ldg(&g_wn[n0]);
                    const float wn1 = __ldg(&g_wn[n0 + 1]);
                    const float s00 = wn0 - 2.f * acc[f][j][0];
                    const float s01 = wn1 - 2.f * acc[f][j][1];
                    const float s10 = wn0 - 2.f * acc[f][j][2];
                    const float s11 = wn1 - 2.f * acc[f][j][3];
                    const int t0 = 2 * f, t1 = 2 * f + 1;
                    top2_ins(s00, n0,     bv[t0], bi[t0], bv2[t0]);
                    top2_ins(s01, n0 + 1, bv[t0], bi[t0], bv2[t0]);
                    top2_ins(s10, n0,     bv[t1], bi[t1], bv2[t1]);
                    top2_ins(s11, n0 + 1, bv[t1], bi[t1], bv2[t1]);
                    acc[f][j][0] = 0.f; acc[f][j][1] = 0.f;
                    acc[f][j][2] = 0.f; acc[f][j][3] = 0.f;
                }
            }
        }
    }

#pragma unroll
    for (int off = 1; off <= 2; off <<= 1) {
#pragma unroll
        for (int t = 0; t < 8; t++) {
            float ov1 = __shfl_xor_sync(0xffffffffu, bv[t], off);
            int   oi1 = __shfl_xor_sync(0xffffffffu, bi[t], off);
            float ov2 = __shfl_xor_sync(0xffffffffu, bv2[t], off);
            top2_mrg(ov1, oi1, ov2, bv[t], bi[t], bv2[t]);
        }
    }

    __syncthreads();
    float* red_val  = (float*)sm;
    int*   red_idx  = (int*)(sm + 2048);
    float* red_val2 = (float*)(sm + 4096);

    if ((lane & 3) == 0) {
        const int g = lane >> 2;
#pragma unroll
        for (int t = 0; t < 8; t++) {
            const int row = warp_m * 64 + (t >> 1) * 16 + (t & 1) * 8 + g;
            red_val[row * 4 + warp_n]  = bv[t];
            red_idx[row * 4 + warp_n]  = bi[t];
            red_val2[row * 4 + warp_n] = bv2[t];
        }
    }
    __syncthreads();

    if (tid < BM) {
        float v1 = -FLT_MAX, v2 = -FLT_MAX;
        int   i1 = 0x7fffffff;
#pragma unroll
        for (int wn = 0; wn < 4; wn++)
            top2_mrg(red_val[tid * 4 + wn], red_idx[tid * 4 + wn],
                     red_val2[tid * 4 + wn], v1, i1, v2);
        const int tok = mbase + tid;
        g_pval[tok * SPLIT + sidx]  = v1;
        g_pidx[tok * SPLIT + sidx]  = i1;
        g_pval2[tok * SPLIT + sidx] = v2;
    }
}

__global__ __launch_bounds__(256, 2)
void vq_hybrid_kernel() {
    const int bid = blockIdx.x;
    const int mbase = (bid >> 4) * BM;
    const int sidx = bid & 15;
    if (sidx < FSPLITS)
        ffma_path(dynsmem, threadIdx.x, mbase, sidx);
    else
        mma_path(dynsmem, threadIdx.x, mbase, sidx);
}

// ---------------- combine split partials + flag + gather ----------------
__global__ void reduce_gather_kernel(const float* __restrict__ wt, float* __restrict__ out) {
    const int tok = blockIdx.x;
    float v1 = -FLT_MAX, v2 = -FLT_MAX;
    int   i1 = 0x7fffffff;
#pragma unroll
    for (int s = 0; s < SPLIT; s++)
        top2_mrg(g_pval[tok * SPLIT + s], g_pidx[tok * SPLIT + s],
                 g_pval2[tok * SPLIT + s], v1, i1, v2);
    const int flag = (v1 - v2 < MARGIN) ? 1 : 0;
    if (threadIdx.x == 0) g_flag[tok] = flag;
    if (!flag) {
        const float4 v = *(const float4*)(wt + (size_t)i1 * DIM + threadIdx.x * 4);
        *(float4*)(out + (size_t)tok * DIM + threadIdx.x * 4) = v;
    }
}

// ---------------- exact fp32 rescue for flagged tokens ----------------
__global__ __launch_bounds__(256)
void rescue_kernel(const float* __restrict__ x, const float* __restrict__ wt,
                   float* __restrict__ out) {
    const int tok = blockIdx.x;
    if (!g_flag[tok]) return;

    __shared__ float xs[DIM];
    __shared__ float rv[8];
    __shared__ int   ri[8];
    __shared__ int   widx;

    const int tid = threadIdx.x;
    if (tid < DIM / 4)
        *(float4*)(xs + tid * 4) = *(const float4*)(x + (size_t)tok * DIM + tid * 4);
    __syncthreads();

    float bv = -FLT_MAX;
    int   bi = 0x7fffffff;
    for (int n = tid; n < KW; n += 256) {
        const float* wr = wt + (size_t)n * DIM;
        float d = 0.f;
#pragma unroll
        for (int c = 0; c < DIM / 4; c++) {
            const float4 wv = __ldg((const float4*)(wr + c * 4));
            const float4 xv = *(const float4*)(xs + c * 4);
            d += xv.x * wv.x + xv.y * wv.y + xv.z * wv.z + xv.w * wv.w;
        }
        const float sc = __ldg(&g_wn[n]) - 2.f * d;
        if (sc > bv || (sc == bv && n < bi)) { bv = sc; bi = n; }
    }
#pragma unroll
    for (int off = 16; off >= 1; off >>= 1) {
        float ov = __shfl_xor_sync(0xffffffffu, bv, off);
        int   oi = __shfl_xor_sync(0xffffffffu, bi, off);
        if (ov > bv || (ov == bv && oi < bi)) { bv = ov; bi = oi; }
    }
    if ((tid & 31) == 0) { rv[tid >> 5] = bv; ri[tid >> 5] = bi; }
    __syncthreads();
    if (tid == 0) {
        float v = rv[0]; int i = ri[0];
#pragma unroll
        for (int wg = 1; wg < 8; wg++)
            if (rv[wg] > v || (rv[wg] == v && ri[wg] < i)) { v = rv[wg]; i = ri[wg]; }
        widx = i;
    }
    __syncthreads();
    const int sel = widx;
    if (tid < DIM / 4) {
        const float4 v = *(const float4*)(wt + (size_t)sel * DIM + tid * 4);
        *(float4*)(out + (size_t)tok * DIM + tid * 4) = v;
    }
}

// ---------------- launch ----------------
extern "C" void kernel_launch(void* const* d_in, const int* in_sizes, int n_in,
                              void* d_out, int out_size) {
    const float* x  = (const float*)d_in[0];   // [16384, 256]
    const float* wt = (const float*)d_in[1];   // [8192, 256]
    float* out = (float*)d_out;

    cudaFuncSetAttribute(vq_hybrid_kernel, cudaFuncAttributeMaxDynamicSharedMemorySize,
                         SMEM_BYTES);

    {
        float* xT = 0; float* wT = 0;
        cudaGetSymbolAddress((void**)&xT, g_xT);
        cudaGetSymbolAddress((void**)&wT, g_wT);
        dim3 bt(32, 8);
        transpose_kernel<<<dim3(DIM / 32, TOKENS / 32), bt>>>(x, xT, TOKENS);
        transpose_kernel<<<dim3(DIM / 32, KW / 32), bt>>>(wt, wT, KW);
        convert_norm_kernel<<<TOKENS * DIM / 4 / 256 + KW / 256, 256>>>(x, wt);
    }

    vq_hybrid_kernel<<<(TOKENS / BM) * SPLIT, 256, SMEM_BYTES>>>();

    reduce_gather_kernel<<<TOKENS, 64>>>(wt, out);
    rescue_kernel<<<TOKENS, 256>>>(x, wt, out);
}

// round 16
// speedup vs baseline: 3.0655x; 3.0655x over previous
#include <cuda_runtime.h>
#include <stdint.h>

typedef unsigned long long ull;

#define TOKENS 16384
#define DIM    256
#define KW     8192

#define BM     128
#define BN     128
#define BK     32
#define SPLIT  16
#define NRANGE (KW / SPLIT)             // 512 codes per CTA
#define STAGES ((NRANGE / BN) * (DIM / BK))   // 4 * 8 = 32
#define SW     128                       // smem row width (floats)
#define TILEB  (BK * SW * 4)             // 16384 bytes per tile
#define BUFB   (2 * TILEB)               // 32768
#define NBUF   3
#define SMEM_BYTES (NBUF * BUFB)         // 98304 -> 2 CTAs/SM

__device__ float g_wn[KW];
__device__ float g_pval[TOKENS * SPLIT];
__device__ int   g_pidx[TOKENS * SPLIT];
__device__ float g_xT[(size_t)DIM * TOKENS];   // [d][token]
__device__ float g_wT[(size_t)DIM * KW];       // [d][code]

// ---------------- helpers ----------------
__device__ __forceinline__ uint32_t smem_u32(const void* p) {
    uint32_t a;
    asm("{ .reg .u64 t; cvta.to.shared.u64 t, %1; cvt.u32.u64 %0, t; }" : "=r"(a) : "l"(p));
    return a;
}
#define CP_ASYNC16(dst, src) \
    asm volatile("cp.async.cg.shared.global [%0], [%1], 16;" :: "r"(dst), "l"(src) : "memory")

// ---------------- prepass: transpose + weight norms ----------------
__global__ void transpose_kernel(const float* __restrict__ src, float* __restrict__ dst,
                                 int rows, int cols) {
    __shared__ float t[32][33];
    const int c0 = blockIdx.x * 32;
    const int r0 = blockIdx.y * 32;
#pragma unroll
    for (int i = 0; i < 4; i++)
        t[threadIdx.y + 8 * i][threadIdx.x] =
            src[(size_t)(r0 + threadIdx.y + 8 * i) * cols + c0 + threadIdx.x];
    __syncthreads();
#pragma unroll
    for (int i = 0; i < 4; i++)
        dst[(size_t)(c0 + threadIdx.y + 8 * i) * rows + r0 + threadIdx.x] =
            t[threadIdx.x][threadIdx.y + 8 * i];
}

__global__ void wnorm_kernel(const float* __restrict__ w) {
    int k = blockIdx.x * 256 + threadIdx.x;
    const float4* row = (const float4*)(w + (size_t)k * DIM);
    float s = 0.f;
#pragma unroll
    for (int i = 0; i < DIM / 4; i++) {
        float4 v = row[i];
        s += v.x * v.x + v.y * v.y + v.z * v.z + v.w * v.w;
    }
    g_wn[k] = s;
}

// ---------------- main FFMA2 kernel (R10 chassis + serpentine FFMA2 order) ----------------
// grid (TOKENS/BM, SPLIT) = (128, 16) = 2048 CTAs -> 6.92 waves @2 CTA/SM
// block 128 threads: tx = tid&15 (codes), ty = tid>>4 (token groups)
extern __shared__ char dynsmem[];

__device__ __forceinline__ void load_stage(uint32_t sbase, int gs, int tid,
                                           int mbase, int nbase0) {
    if (gs < STAGES) {
        const int buf = gs % NBUF;
        const int dt = (gs & 7) * BK;
        const int nb = nbase0 + (gs >> 3) * BN;
        const uint32_t xb = sbase + buf * BUFB;
        const uint32_t wb = xb + TILEB;
#pragma unroll
        for (int i = 0; i < 8; i++) {
            const int idx = tid + 128 * i;        // 0..1023
            const int row = idx >> 5;             // 0..31 (k within stage)
            const int col = idx & 31;             // 16B chunk (4 floats)
            CP_ASYNC16(xb + row * (SW * 4) + col * 16,
                       g_xT + (size_t)(dt + row) * TOKENS + mbase + col * 4);
            CP_ASYNC16(wb + row * (SW * 4) + col * 16,
                       g_wT + (size_t)(dt + row) * KW + nb + col * 4);
        }
    }
    asm volatile("cp.async.commit_group;" ::: "memory");
}

__global__ __launch_bounds__(128, 2)
void vq_ffma_kernel() {
    char* sm = dynsmem;
    const uint32_t sbase = smem_u32(sm);
    const int tid = threadIdx.x;
    const int tx = tid & 15;
    const int ty = tid >> 4;
    const int mbase = blockIdx.x * BM;
    const int nbase0 = blockIdx.y * NRANGE;

    ull acc[8][8];
#pragma unroll
    for (int p = 0; p < 8; p++)
#pragma unroll
        for (int j = 0; j < 8; j++) acc[p][j] = 0ull;

    float bv[16];
    int   bi[16];
#pragma unroll
    for (int t = 0; t < 16; t++) { bv[t] = -3.402823e38f; bi[t] = 0x7fffffff; }

    load_stage(sbase, 0, tid, mbase, nbase0);

    for (int gs = 0; gs < STAGES; gs++) {
        load_stage(sbase, gs + 1, tid, mbase, nbase0);       // commits even if empty
        asm volatile("cp.async.wait_group 1;" ::: "memory"); // stage gs resident
        __syncthreads();

        const float* xsp = (const float*)(sm + (gs % NBUF) * BUFB);
        const float* wsp = (const float*)(sm + (gs % NBUF) * BUFB + TILEB);

#pragma unroll
        for (int k = 0; k < BK; k++) {
            ull x2[8];
#pragma unroll
            for (int p = 0; p < 8; p++)
                x2[p] = *(const ull*)(&xsp[k * SW + ty * 16 + 2 * p]);  // token-pair LDS.64
            ull w2[8];
#pragma unroll
            for (int j = 0; j < 8; j++) {
                float wv = wsp[k * SW + tx + 16 * j];
                asm("mov.b64 %0, {%1, %1};" : "=l"(w2[j]) : "f"(wv));
            }
            // serpentine: within row p the x operand repeats (slot-A reuse);
            // at each row boundary the w operand repeats (slot-B reuse)
#pragma unroll
            for (int p = 0; p < 8; p++) {
#pragma unroll
                for (int jj = 0; jj < 8; jj++) {
                    const int j = (p & 1) ? (7 - jj) : jj;
                    asm("fma.rn.f32x2 %0, %1, %2, %0;"
                        : "+l"(acc[p][j]) : "l"(x2[p]), "l"(w2[j]));
                }
            }
        }

        if ((gs & 7) == 7) {
            // chunk epilogue: score = ||w||^2 - 2 x.w ; streaming argmax
            const int nb = nbase0 + (gs >> 3) * BN;
#pragma unroll
            for (int j = 0; j < 8; j++) {
                const int n = nb + tx + 16 * j;
                const float wn = __ldg(&g_wn[n]);
#pragma unroll
                for (int p = 0; p < 8; p++) {
                    float lo, hi;
                    asm("mov.b64 {%0, %1}, %2;" : "=f"(lo), "=f"(hi) : "l"(acc[p][j]));
                    const float s0 = wn - 2.f * lo;
                    const float s1 = wn - 2.f * hi;
                    const int t0 = 2 * p, t1 = 2 * p + 1;
                    if (s0 > bv[t0] || (s0 == bv[t0] && n < bi[t0])) { bv[t0] = s0; bi[t0] = n; }
                    if (s1 > bv[t1] || (s1 == bv[t1] && n < bi[t1])) { bv[t1] = s1; bi[t1] = n; }
                    acc[p][j] = 0ull;
                }
            }
        }
    }

    // reduce across the 16 tx lanes (xor stays within 16-lane halves; ty preserved)
#pragma unroll
    for (int off = 8; off >= 1; off >>= 1) {
#pragma unroll
        for (int t = 0; t < 16; t++) {
            float ov = __shfl_xor_sync(0xffffffffu, bv[t], off);
            int   oi = __shfl_xor_sync(0xffffffffu, bi[t], off);
            if (ov > bv[t] || (ov == bv[t] && oi < bi[t])) { bv[t] = ov; bi[t] = oi; }
        }
    }

    if (tx == 0) {
        const int s = blockIdx.y;
#pragma unroll
        for (int t = 0; t < 16; t++) {
            const int tok = mbase + ty * 16 + t;
            g_pval[tok * SPLIT + s] = bv[t];
            g_pidx[tok * SPLIT + s] = bi[t];
        }
    }
}

// ---------------- combine split partials + gather ----------------
__global__ void reduce_gather_kernel(const float* __restrict__ wt, float* __restrict__ out) {
    const int tok = blockIdx.x;
    float bv = -3.402823e38f;
    int   bi = 0x7fffffff;
#pragma unroll
    for (int s = 0; s < SPLIT; s++) {
        const float v = g_pval[tok * SPLIT + s];
        const int   i = g_pidx[tok * SPLIT + s];
        if (v > bv || (v == bv && i < bi)) { bv = v; bi = i; }
    }
    const float4 v = *(const float4*)(wt + (size_t)bi * DIM + threadIdx.x * 4);
    *(float4*)(out + (size_t)tok * DIM + threadIdx.x * 4) = v;
}

// ---------------- launch ----------------
extern "C" void kernel_launch(void* const* d_in, const int* in_sizes, int n_in,
                              void* d_out, int out_size) {
    const float* x  = (const float*)d_in[0];   // [16384, 256]
    const float* wt = (const float*)d_in[1];   // [8192, 256]
    float* out = (float*)d_out;

    cudaFuncSetAttribute(vq_ffma_kernel, cudaFuncAttributeMaxDynamicSharedMemorySize, SMEM_BYTES);

    {
        float* xT = 0; float* wT = 0;
        cudaGetSymbolAddress((void**)&xT, g_xT);
        cudaGetSymbolAddress((void**)&wT, g_wT);
        dim3 bt(32, 8);
        transpose_kernel<<<dim3(DIM / 32, TOKENS / 32), bt>>>(x, xT, TOKENS, DIM);
        transpose_kernel<<<dim3(DIM / 32, KW / 32), bt>>>(wt, wT, KW, DIM);
        wnorm_kernel<<<KW / 256, 256>>>(wt);
    }

    dim3 grid(TOKENS / BM, SPLIT);
    vq_ffma_kernel<<<grid, 128, SMEM_BYTES>>>();

    reduce_gather_kernel<<<TOKENS, 64>>>(wt, out);
}